// round 13
// baseline (speedup 1.0000x reference)
#include <cuda_runtime.h>
#include <cuda_bf16.h>
#include <cstdint>

// Problem constants
#define BATCH 16
#define TLEN 8192
#define DIM 512
#define SPAN 8
#define NSEG 1024
#define NROW 16384
#define NCODE 8192
#define NCTILE 64            // NCODE / BN

// Output layout (flattened tuple: quantized_out, total_loss, idx_out, boundaries)
#define OUT_Q_SIZE   ((size_t)BATCH*TLEN*DIM)
#define OUT_LOSS_OFF (OUT_Q_SIZE)
#define OUT_IDX_OFF  (OUT_LOSS_OFF + 1)
#define OUT_BND_OFF  (OUT_IDX_OFF + (size_t)BATCH*TLEN)

#define DELTA 0.125f
#define POOL_SCALE 56.f
#define EMB_SCALE 1100.f
#define SCORE_MUL (2.f / (56.f * 1100.f))
#define CAND1_CAP (1<<25)
#define CAND_CAP  (1<<21)
#define CBUF_CAP  2048

// GEMM tiling (int8): BM=BN=128, 8 warps (4x2), warp tile 32x64,
// stage K = 128 int8 elements (128 bytes), 4 k32 slices per stage
#define BM 128
#define BN 128
#define BKB 128
#define SSTRB 144                // 128 + 16 pad bytes, conflict-free ldmatrix
#define HMMA_DSMEM (2*(BM+BN)*SSTRB)   // 73728 bytes

// ---------------- device scratch ----------------
__device__ float g_pooled[NROW * DIM];
__device__ signed char g_pooled_i8[NROW * DIM];
__device__ signed char g_emb_i8[NCODE * DIM];
__device__ float g_e2[NCODE];
__device__ unsigned g_tilemin[NROW * NCTILE];
__device__ float g_thr[NROW];
__device__ unsigned long long g_best[NROW];
__device__ float g_partial[NROW];
__device__ int g_bcount;
__device__ int g_nc1;
__device__ int g_ncand;
__device__ uint2 g_cand1[CAND1_CAP];
__device__ unsigned int g_cand[CAND_CAP];

// ---------------- helpers ----------------
__device__ __forceinline__ uint32_t smem_u32(const void* p) {
    uint32_t a;
    asm("{ .reg .u64 t; cvta.to.shared.u64 t, %1; cvt.u32.u64 %0, t; }" : "=r"(a) : "l"(p));
    return a;
}
__device__ __forceinline__ unsigned ord_u32(float s) {
    unsigned u = __float_as_uint(s);
    return (u & 0x80000000u) ? ~u : (u | 0x80000000u);
}
__device__ __forceinline__ float unord_f32(unsigned v) {
    unsigned u = (v & 0x80000000u) ? (v & 0x7FFFFFFFu) : ~v;
    return __uint_as_float(u);
}
__device__ __forceinline__ int q8(float v, float s) {
    float x = v * s;
    x = fminf(fmaxf(x, -127.f), 127.f);
    return __float2int_rn(x);
}

// ---------------- init ----------------
__global__ void atvq_init_kernel() {
    int i = blockIdx.x * blockDim.x + threadIdx.x;
    if (i < NROW) g_best[i] = ~0ULL;
    if (i == 0) { g_bcount = 0; g_nc1 = 0; g_ncand = 0; }
}

// ---------------- e2 (fp32 exact) ----------------
__global__ void atvq_e2_kernel(const float* __restrict__ emb) {
    int gw = (blockIdx.x * blockDim.x + threadIdx.x) >> 5;
    int lane = threadIdx.x & 31;
    if (gw >= NCODE) return;
    const float4* e = (const float4*)(emb + (size_t)gw * DIM);
    float s = 0.f;
    #pragma unroll
    for (int i = 0; i < 4; i++) {
        float4 v = e[lane + i * 32];
        s += v.x * v.x + v.y * v.y + v.z * v.z + v.w * v.w;
    }
    #pragma unroll
    for (int off = 16; off; off >>= 1) s += __shfl_xor_sync(0xffffffffu, s, off);
    if (lane == 0) g_e2[gw] = s;
}

// ---------------- emb -> int8 (scaled) ----------------
__global__ void atvq_embconv_kernel(const float* __restrict__ emb) {
    int i = blockIdx.x * blockDim.x + threadIdx.x;   // one float4 per thread
    float4 v = ((const float4*)emb)[i];
    int b0 = q8(v.x, EMB_SCALE) & 0xFF;
    int b1 = q8(v.y, EMB_SCALE) & 0xFF;
    int b2 = q8(v.z, EMB_SCALE) & 0xFF;
    int b3 = q8(v.w, EMB_SCALE) & 0xFF;
    ((unsigned*)g_emb_i8)[i] = (unsigned)(b0 | (b1 << 8) | (b2 << 16) | (b3 << 24));
}

// ---------------- fused segment mean pool + boundary predictor ----------------
__global__ void atvq_pool_boundary_kernel(const float* __restrict__ x,
                                          const float* __restrict__ Wb,
                                          const float* __restrict__ bb,
                                          float* __restrict__ out) {
    int row = blockIdx.x;
    int b = row >> 10, seg = row & 1023;
    int t = threadIdx.x;
    float w0 = Wb[t], w1 = Wb[t + 256];
    const float* xb = x + ((size_t)b * TLEN + (size_t)seg * SPAN) * DIM;
    float s0 = 0.f, s1 = 0.f;
    float p[SPAN];
    #pragma unroll
    for (int r = 0; r < SPAN; r++) {
        float v0 = xb[(size_t)r * DIM + t];
        float v1 = xb[(size_t)r * DIM + t + 256];
        s0 += v0; s1 += v1;
        p[r] = v0 * w0 + v1 * w1;
    }
    float m0 = s0 * 0.125f, m1 = s1 * 0.125f;
    g_pooled[(size_t)row * DIM + t] = m0;
    g_pooled[(size_t)row * DIM + t + 256] = m1;
    g_pooled_i8[(size_t)row * DIM + t] = (signed char)q8(m0, POOL_SCALE);
    g_pooled_i8[(size_t)row * DIM + t + 256] = (signed char)q8(m1, POOL_SCALE);

    #pragma unroll
    for (int r = 0; r < SPAN; r++) {
        #pragma unroll
        for (int off = 16; off; off >>= 1) p[r] += __shfl_xor_sync(0xffffffffu, p[r], off);
    }
    __shared__ float ws[8][SPAN];
    int warp = t >> 5, lane = t & 31;
    if (lane == 0) {
        #pragma unroll
        for (int r = 0; r < SPAN; r++) ws[warp][r] = p[r];
    }
    __syncthreads();
    if (t < SPAN) {
        float sum = bb[0];
        #pragma unroll
        for (int w = 0; w < 8; w++) sum += ws[w][t];
        float bnd = (sum > 0.f) ? 1.f : 0.f;
        out[OUT_BND_OFF + (size_t)b * TLEN + (size_t)seg * SPAN + t] = bnd;
        if (bnd > 0.f) atomicAdd(&g_bcount, 1);
    }
}

// ---------------- int8 IMMA approx-score GEMM + in-epilogue candidates ------
// BM=128 x BN=128, 8 warps (4x2), warp tile 32x64, 128B stages, 2-stage cp.async
__global__ __launch_bounds__(256, 2)
void atvq_hmma_kernel() {
    extern __shared__ char dyn[];
    char* sAb = dyn;                          // 2 stages x BM*SSTRB
    char* sBb = dyn + 2 * BM * SSTRB;         // 2 stages x BN*SSTRB
    __shared__ unsigned s_rmin[BM];
    __shared__ int s_cnt, s_gbase;

    int tid = threadIdx.x, lane = tid & 31, wid = tid >> 5;
    int wm = wid & 3, wn = wid >> 2;            // 4 x 2 warp grid, 32x64 tiles
    int rowBase = blockIdx.y * BM;
    int colBase = blockIdx.x * BN;

    for (int i = tid; i < BM; i += 256) s_rmin[i] = 0xFFFFFFFFu;
    if (tid == 0) s_cnt = 0;

    int acc[2][8][4];
    #pragma unroll
    for (int a = 0; a < 2; a++)
        #pragma unroll
        for (int b = 0; b < 8; b++)
            #pragma unroll
            for (int c = 0; c < 4; c++) acc[a][b][c] = 0;

    // stage loader: A+B each 128 rows x 128 int8 bytes = 1024 x 16B chunks, 4/thread
    #define LOAD_STAGE(s, kt) do {                                              \
        char* stA = sAb + (s) * BM * SSTRB;                                     \
        char* stB = sBb + (s) * BN * SSTRB;                                     \
        _Pragma("unroll")                                                       \
        for (int q = 0; q < 4; q++) {                                           \
            int ch = tid + q * 256;                                             \
            int r = ch >> 3, c8 = ch & 7;                                       \
            uint32_t da = smem_u32(&stA[r * SSTRB + c8 * 16]);                  \
            const void* ga = &g_pooled_i8[(size_t)(rowBase + r) * DIM + (kt) + c8 * 16]; \
            asm volatile("cp.async.ca.shared.global [%0], [%1], 16;" :: "r"(da), "l"(ga)); \
            uint32_t db = smem_u32(&stB[r * SSTRB + c8 * 16]);                  \
            const void* gb = &g_emb_i8[(size_t)(colBase + r) * DIM + (kt) + c8 * 16]; \
            asm volatile("cp.async.ca.shared.global [%0], [%1], 16;" :: "r"(db), "l"(gb)); \
        }                                                                       \
    } while (0)

    LOAD_STAGE(0, 0);
    asm volatile("cp.async.commit_group;" ::: "memory");

    const int NT = DIM / BKB;   // 4
    for (int t = 0; t < NT; t++) {
        if (t + 1 < NT) LOAD_STAGE((t + 1) & 1, (t + 1) * BKB);
        asm volatile("cp.async.commit_group;" ::: "memory");
        asm volatile("cp.async.wait_group 1;" ::: "memory");
        __syncthreads();
        int s = t & 1;
        char* stA = sAb + s * BM * SSTRB;
        char* stB = sBb + s * BN * SSTRB;
        #pragma unroll
        for (int ks = 0; ks < BKB; ks += 32) {      // 4 x k32 slices
            uint32_t af[2][4], bf[4][4];
            #pragma unroll
            for (int mf = 0; mf < 2; mf++) {
                uint32_t addr = smem_u32(
                    &stA[(wm * 32 + mf * 16 + (lane & 15)) * SSTRB + ks + (lane >> 4) * 16]);
                asm volatile("ldmatrix.sync.aligned.m8n8.x4.shared.b16 {%0,%1,%2,%3},[%4];"
                             : "=r"(af[mf][0]), "=r"(af[mf][1]), "=r"(af[mf][2]), "=r"(af[mf][3])
                             : "r"(addr));
            }
            #pragma unroll
            for (int nb = 0; nb < 4; nb++) {
                uint32_t addr = smem_u32(
                    &stB[(wn * 64 + nb * 16 + (lane & 15)) * SSTRB + ks + (lane >> 4) * 16]);
                asm volatile("ldmatrix.sync.aligned.m8n8.x4.shared.b16 {%0,%1,%2,%3},[%4];"
                             : "=r"(bf[nb][0]), "=r"(bf[nb][1]), "=r"(bf[nb][2]), "=r"(bf[nb][3])
                             : "r"(addr));
            }
            #pragma unroll
            for (int mf = 0; mf < 2; mf++) {
                #pragma unroll
                for (int nb = 0; nb < 4; nb++) {
                    asm volatile(
                        "mma.sync.aligned.m16n8k32.row.col.s32.s8.s8.s32 "
                        "{%0,%1,%2,%3}, {%4,%5,%6,%7}, {%8,%9}, {%0,%1,%2,%3};"
                        : "+r"(acc[mf][nb*2+0][0]), "+r"(acc[mf][nb*2+0][1]),
                          "+r"(acc[mf][nb*2+0][2]), "+r"(acc[mf][nb*2+0][3])
                        : "r"(af[mf][0]), "r"(af[mf][1]), "r"(af[mf][2]), "r"(af[mf][3]),
                          "r"(bf[nb][0]), "r"(bf[nb][2]));
                    asm volatile(
                        "mma.sync.aligned.m16n8k32.row.col.s32.s8.s8.s32 "
                        "{%0,%1,%2,%3}, {%4,%5,%6,%7}, {%8,%9}, {%0,%1,%2,%3};"
                        : "+r"(acc[mf][nb*2+1][0]), "+r"(acc[mf][nb*2+1][1]),
                          "+r"(acc[mf][nb*2+1][2]), "+r"(acc[mf][nb*2+1][3])
                        : "r"(af[mf][0]), "r"(af[mf][1]), "r"(af[mf][2]), "r"(af[mf][3]),
                          "r"(bf[nb][1]), "r"(bf[nb][3]));
                }
            }
        }
        __syncthreads();
    }

    // ---- epilogue pass 1: per-row minima (convert on the fly, no float storage)
    unsigned mn[2][2] = {{0xFFFFFFFFu, 0xFFFFFFFFu}, {0xFFFFFFFFu, 0xFFFFFFFFu}};
    #pragma unroll
    for (int mf = 0; mf < 2; mf++) {
        #pragma unroll
        for (int nf = 0; nf < 8; nf++) {
            int c = colBase + wn * 64 + nf * 8 + (lane & 3) * 2;
            float e2a = g_e2[c], e2b = g_e2[c + 1];
            unsigned u;
            u = ord_u32(e2a - SCORE_MUL * (float)acc[mf][nf][0]); if (u < mn[mf][0]) mn[mf][0] = u;
            u = ord_u32(e2b - SCORE_MUL * (float)acc[mf][nf][1]); if (u < mn[mf][0]) mn[mf][0] = u;
            u = ord_u32(e2a - SCORE_MUL * (float)acc[mf][nf][2]); if (u < mn[mf][1]) mn[mf][1] = u;
            u = ord_u32(e2b - SCORE_MUL * (float)acc[mf][nf][3]); if (u < mn[mf][1]) mn[mf][1] = u;
        }
    }
    #pragma unroll
    for (int mf = 0; mf < 2; mf++)
        #pragma unroll
        for (int p = 0; p < 2; p++) {
            unsigned m = mn[mf][p];
            unsigned o = __shfl_xor_sync(0xffffffffu, m, 1); if (o < m) m = o;
            o = __shfl_xor_sync(0xffffffffu, m, 2); if (o < m) m = o;
            if ((lane & 3) == 0)
                atomicMin(&s_rmin[wm * 32 + mf * 16 + p * 8 + (lane >> 2)], m);
        }
    __syncthreads();

    if (tid < BM)
        g_tilemin[(size_t)(rowBase + tid) * NCTILE + blockIdx.x] = s_rmin[tid];

    // ---- epilogue pass 2: candidate push (re-convert; identical values) ----
    uint2* cbuf = (uint2*)dyn;     // alias stage memory (done with it)
    #pragma unroll
    for (int mf = 0; mf < 2; mf++) {
        int lr_lo = wm * 32 + mf * 16 + (lane >> 2);
        float thr_lo = unord_f32(s_rmin[lr_lo]) + DELTA;
        float thr_hi = unord_f32(s_rmin[lr_lo + 8]) + DELTA;
        #pragma unroll
        for (int nf = 0; nf < 8; nf++) {
            int c = colBase + wn * 64 + nf * 8 + (lane & 3) * 2;
            float e2a = g_e2[c], e2b = g_e2[c + 1];
            #pragma unroll
            for (int q = 0; q < 4; q++) {
                float e2v = (q & 1) ? e2b : e2a;
                float s = e2v - SCORE_MUL * (float)acc[mf][nf][q];
                int lr = (q < 2) ? lr_lo : lr_lo + 8;
                float thr = (q < 2) ? thr_lo : thr_hi;
                if (s <= thr) {
                    unsigned packed = ((unsigned)(rowBase + lr) << 13) | (unsigned)(c + (q & 1));
                    int slot = atomicAdd(&s_cnt, 1);
                    uint2 e = make_uint2(__float_as_uint(s), packed);
                    if (slot < CBUF_CAP) cbuf[slot] = e;
                    else {
                        int g = atomicAdd(&g_nc1, 1);
                        if (g < CAND1_CAP) g_cand1[g] = e;
                    }
                }
            }
        }
    }
    __syncthreads();
    if (tid == 0) {
        int n = s_cnt < CBUF_CAP ? s_cnt : CBUF_CAP;
        s_gbase = atomicAdd(&g_nc1, n);
        s_cnt = n;
    }
    __syncthreads();
    int n = s_cnt, gb = s_gbase;
    for (int i = tid; i < n; i += 256) {
        int g = gb + i;
        if (g < CAND1_CAP) g_cand1[g] = cbuf[i];
    }
}

// ---------------- global thresholds from tile minima ----------------
__global__ void atvq_thr_kernel() {
    int warp = (blockIdx.x * blockDim.x + threadIdx.x) >> 5;
    int lane = threadIdx.x & 31;
    if (warp >= NROW) return;
    const unsigned* tm = &g_tilemin[(size_t)warp * NCTILE];
    unsigned m = tm[lane], o = tm[lane + 32];
    if (o < m) m = o;
    #pragma unroll
    for (int off = 16; off; off >>= 1) {
        o = __shfl_xor_sync(0xffffffffu, m, off); if (o < m) m = o;
    }
    if (lane == 0) g_thr[warp] = unord_f32(m) + DELTA;
}

// ---------------- filter stage-1 candidates ----------------
__global__ void atvq_filter_kernel() {
    int n1 = g_nc1; if (n1 > CAND1_CAP) n1 = CAND1_CAP;
    int lane = threadIdx.x & 31;
    int gwarp = (blockIdx.x * blockDim.x + threadIdx.x) >> 5;
    int nwarp = (gridDim.x * blockDim.x) >> 5;
    for (int base = gwarp * 32; base < n1; base += nwarp * 32) {
        int i = base + lane;
        bool keep = false;
        uint2 e;
        if (i < n1) {
            e = g_cand1[i];
            keep = (__uint_as_float(e.x) <= g_thr[e.y >> 13]);
        }
        unsigned mask = __ballot_sync(0xffffffffu, keep);
        if (mask) {
            int cnt = __popc(mask);
            int pos = 0;
            if (lane == __ffs(mask) - 1) pos = atomicAdd(&g_ncand, cnt);
            pos = __shfl_sync(0xffffffffu, pos, __ffs(mask) - 1);
            if (keep) {
                int r = __popc(mask & ((1u << lane) - 1u));
                if (pos + r < CAND_CAP) g_cand[pos + r] = e.y;
            }
        }
    }
}

// ---------------- exact fp32 rerank ----------------
__global__ void atvq_rerank_kernel(const float* __restrict__ emb) {
    int gw = (blockIdx.x * blockDim.x + threadIdx.x) >> 5;
    int lane = threadIdx.x & 31;
    int nwarp = (gridDim.x * blockDim.x) >> 5;
    int n = g_ncand; if (n > CAND_CAP) n = CAND_CAP;
    for (int c = gw; c < n; c += nwarp) {
        unsigned e = g_cand[c];
        int row = e >> 13, k = e & (NCODE - 1);
        const float4* xp = (const float4*)&g_pooled[(size_t)row * DIM];
        const float4* ep = (const float4*)&emb[(size_t)k * DIM];
        float dot = 0.f;
        #pragma unroll
        for (int i = 0; i < 4; i++) {
            float4 a = xp[lane + i * 32];
            float4 b = ep[lane + i * 32];
            dot += a.x * b.x + a.y * b.y + a.z * b.z + a.w * b.w;
        }
        #pragma unroll
        for (int off = 16; off; off >>= 1) dot += __shfl_xor_sync(0xffffffffu, dot, off);
        if (lane == 0) {
            float s = g_e2[k] - 2.f * dot;
            unsigned long long key = ((unsigned long long)ord_u32(s) << 32) | (unsigned)k;
            atomicMin(&g_best[row], key);
        }
    }
}

// ---------------- gather + expand + per-row latent-loss partial ----------------
__global__ void atvq_gather_kernel(const float* __restrict__ emb,
                                   float* __restrict__ out) {
    int row = blockIdx.x;
    int t = threadIdx.x;
    int b = row >> 10, seg = row & 1023;
    unsigned long long bv = g_best[row];
    int k = (bv == ~0ULL) ? 0 : (int)(bv & (NCODE - 1));   // safety clamp

    float e0 = emb[(size_t)k * DIM + t];
    float e1 = emb[(size_t)k * DIM + t + 256];
    float p0 = g_pooled[(size_t)row * DIM + t];
    float p1 = g_pooled[(size_t)row * DIM + t + 256];
    float d0 = e0 - p0, d1 = e1 - p1;
    float part = d0 * d0 + d1 * d1;

    size_t base = ((size_t)b * TLEN + (size_t)seg * SPAN) * DIM;
    #pragma unroll
    for (int r = 0; r < SPAN; r++) {
        out[base + (size_t)r * DIM + t] = e0;
        out[base + (size_t)r * DIM + t + 256] = e1;
    }

    #pragma unroll
    for (int off = 16; off; off >>= 1) part += __shfl_xor_sync(0xffffffffu, part, off);
    __shared__ float ws[8];
    int warp = t >> 5, lane = t & 31;
    if (lane == 0) ws[warp] = part;
    __syncthreads();
    if (t == 0) {
        float tot = 0.f;
        #pragma unroll
        for (int w = 0; w < 8; w++) tot += ws[w];
        g_partial[row] = tot;
    }
    if (t < SPAN)
        out[OUT_IDX_OFF + (size_t)b * TLEN + (size_t)seg * SPAN + t] = (float)k;
}

// ---------------- final scalar loss ----------------
__global__ void atvq_finalize_kernel(float* __restrict__ out) {
    __shared__ float sm[256];
    int t = threadIdx.x;
    float s = 0.f;
    for (int i = t; i < NROW; i += 256) s += g_partial[i];
    sm[t] = s;
    __syncthreads();
    for (int st = 128; st; st >>= 1) {
        if (t < st) sm[t] += sm[t + st];
        __syncthreads();
    }
    if (t == 0) {
        float elat = sm[0] / (float)((size_t)NROW * DIM);
        float bmean = (float)g_bcount / (float)(BATCH * TLEN);
        float bl = bmean - (1.0f / SPAN);
        bl = bl * bl;
        out[OUT_LOSS_OFF] = 0.25f * elat + 0.01f * bl;
    }
}

// ---------------- launcher ----------------
extern "C" void kernel_launch(void* const* d_in, const int* in_sizes, int n_in,
                              void* d_out, int out_size) {
    const float* x   = (const float*)d_in[0];
    const float* emb = (const float*)d_in[1];
    const float* Wb  = (const float*)d_in[2];
    const float* bb  = (const float*)d_in[3];
    float* out = (float*)d_out;

    static int attr_done = 0;
    if (!attr_done) {
        cudaFuncSetAttribute(atvq_hmma_kernel,
                             cudaFuncAttributeMaxDynamicSharedMemorySize, HMMA_DSMEM);
        attr_done = 1;
    }

    atvq_init_kernel<<<NROW / 256, 256>>>();
    atvq_e2_kernel<<<NCODE / 8, 256>>>(emb);
    atvq_embconv_kernel<<<(NCODE * DIM / 4) / 256, 256>>>(emb);
    atvq_pool_boundary_kernel<<<NROW, 256>>>(x, Wb, bb, out);

    dim3 ggrid(NCODE / BN, NROW / BM);
    atvq_hmma_kernel<<<ggrid, 256, HMMA_DSMEM>>>();

    atvq_thr_kernel<<<NROW / 8, 256>>>();
    atvq_filter_kernel<<<1024, 256>>>();
    atvq_rerank_kernel<<<512, 256>>>(emb);
    atvq_gather_kernel<<<NROW, 256>>>(emb, out);
    atvq_finalize_kernel<<<1, 256>>>(out);
}

// round 15
// speedup vs baseline: 1.5085x; 1.5085x over previous
#include <cuda_runtime.h>
#include <cuda_bf16.h>
#include <cstdint>

// Problem constants
#define BATCH 16
#define TLEN 8192
#define DIM 512
#define SPAN 8
#define NSEG 1024
#define NROW 16384
#define NCODE 8192
#define NCTILE 64            // NCODE / BN

// Output layout (flattened tuple: quantized_out, total_loss, idx_out, boundaries)
#define OUT_Q_SIZE   ((size_t)BATCH*TLEN*DIM)
#define OUT_LOSS_OFF (OUT_Q_SIZE)
#define OUT_IDX_OFF  (OUT_LOSS_OFF + 1)
#define OUT_BND_OFF  (OUT_IDX_OFF + (size_t)BATCH*TLEN)

#define DELTA 0.125f
#define CAND1_CAP (1<<25)
#define CAND_CAP  (1<<21)
#define CBUF_CAP  2048

// GEMM tiling: BM=BN=128, BK=64, 8 warps (4x2), warp tile 32x64 (R6 proven config)
#define BM 128
#define BN 128
#define BK 64
#define SSTR 72                  // 64 + 8 pad, conflict-free ldmatrix
#define HMMA_DSMEM (2*(BM+BN)*SSTR*2)   // 73728 bytes

// ---------------- device scratch ----------------
__device__ float g_pooled[NROW * DIM];
__device__ __nv_bfloat16 g_pooled_bf[NROW * DIM];
__device__ __nv_bfloat16 g_emb_bf[NCODE * DIM];
__device__ float g_e2[NCODE];
__device__ unsigned g_tilemin[NROW * NCTILE];
__device__ float g_thr[NROW];
__device__ unsigned long long g_best[NROW];
__device__ float g_partial[NROW];
__device__ int g_bcount;
__device__ int g_nc1;
__device__ int g_ncand;
__device__ uint2 g_cand1[CAND1_CAP];
__device__ unsigned int g_cand[CAND_CAP];

// ---------------- helpers ----------------
__device__ __forceinline__ uint32_t smem_u32(const void* p) {
    uint32_t a;
    asm("{ .reg .u64 t; cvta.to.shared.u64 t, %1; cvt.u32.u64 %0, t; }" : "=r"(a) : "l"(p));
    return a;
}
__device__ __forceinline__ unsigned ord_u32(float s) {
    unsigned u = __float_as_uint(s);
    return (u & 0x80000000u) ? ~u : (u | 0x80000000u);
}
__device__ __forceinline__ float unord_f32(unsigned v) {
    unsigned u = (v & 0x80000000u) ? (v & 0x7FFFFFFFu) : ~v;
    return __uint_as_float(u);
}

// ---------------- fused: e2 + emb->bf16 + scalar init ----------------
__global__ void atvq_prep_kernel(const float* __restrict__ emb) {
    if (blockIdx.x == 0 && threadIdx.x == 0) { g_bcount = 0; g_nc1 = 0; g_ncand = 0; }
    int gw = (blockIdx.x * blockDim.x + threadIdx.x) >> 5;
    int lane = threadIdx.x & 31;
    if (gw >= NCODE) return;
    const float4* e = (const float4*)(emb + (size_t)gw * DIM);
    __nv_bfloat162* dst = (__nv_bfloat162*)(g_emb_bf + (size_t)gw * DIM);
    float s = 0.f;
    #pragma unroll
    for (int i = 0; i < 4; i++) {
        int c = lane + i * 32;
        float4 v = e[c];
        s += v.x * v.x + v.y * v.y + v.z * v.z + v.w * v.w;
        dst[c * 2 + 0] = __floats2bfloat162_rn(v.x, v.y);
        dst[c * 2 + 1] = __floats2bfloat162_rn(v.z, v.w);
    }
    #pragma unroll
    for (int off = 16; off; off >>= 1) s += __shfl_xor_sync(0xffffffffu, s, off);
    if (lane == 0) g_e2[gw] = s;
}

// ---------------- fused segment mean pool + boundary predictor ----------------
__global__ void atvq_pool_boundary_kernel(const float* __restrict__ x,
                                          const float* __restrict__ Wb,
                                          const float* __restrict__ bb,
                                          float* __restrict__ out) {
    int row = blockIdx.x;
    int b = row >> 10, seg = row & 1023;
    int t = threadIdx.x;
    float w0 = Wb[t], w1 = Wb[t + 256];
    const float* xb = x + ((size_t)b * TLEN + (size_t)seg * SPAN) * DIM;
    float s0 = 0.f, s1 = 0.f;
    float p[SPAN];
    #pragma unroll
    for (int r = 0; r < SPAN; r++) {
        float v0 = xb[(size_t)r * DIM + t];
        float v1 = xb[(size_t)r * DIM + t + 256];
        s0 += v0; s1 += v1;
        p[r] = v0 * w0 + v1 * w1;
    }
    float m0 = s0 * 0.125f, m1 = s1 * 0.125f;
    g_pooled[(size_t)row * DIM + t] = m0;
    g_pooled[(size_t)row * DIM + t + 256] = m1;
    g_pooled_bf[(size_t)row * DIM + t] = __float2bfloat16(m0);
    g_pooled_bf[(size_t)row * DIM + t + 256] = __float2bfloat16(m1);

    #pragma unroll
    for (int r = 0; r < SPAN; r++) {
        #pragma unroll
        for (int off = 16; off; off >>= 1) p[r] += __shfl_xor_sync(0xffffffffu, p[r], off);
    }
    __shared__ float ws[8][SPAN];
    int warp = t >> 5, lane = t & 31;
    if (lane == 0) {
        #pragma unroll
        for (int r = 0; r < SPAN; r++) ws[warp][r] = p[r];
    }
    __syncthreads();
    if (t < SPAN) {
        float sum = bb[0];
        #pragma unroll
        for (int w = 0; w < 8; w++) sum += ws[w][t];
        float bnd = (sum > 0.f) ? 1.f : 0.f;
        out[OUT_BND_OFF + (size_t)b * TLEN + (size_t)seg * SPAN + t] = bnd;
        if (bnd > 0.f) atomicAdd(&g_bcount, 1);
    }
}

// ---------------- bf16 HMMA approx-score GEMM + in-epilogue candidates -------
// BM=128 x BN=128, 8 warps (4x2), warp tile 32x64, BK=64, 2-stage cp.async
__global__ __launch_bounds__(256, 2)
void atvq_hmma_kernel() {
    extern __shared__ char dyn[];
    __nv_bfloat16* sAb = (__nv_bfloat16*)dyn;                       // 2 x BM*SSTR
    __nv_bfloat16* sBb = (__nv_bfloat16*)(dyn + 2 * BM * SSTR * 2); // 2 x BN*SSTR
    __shared__ unsigned s_rmin[BM];
    __shared__ int s_cnt, s_gbase;

    int tid = threadIdx.x, lane = tid & 31, wid = tid >> 5;
    int wm = wid & 3, wn = wid >> 2;            // 4 x 2 warp grid, 32x64 tiles
    int rowBase = blockIdx.y * BM;
    int colBase = blockIdx.x * BN;

    for (int i = tid; i < BM; i += 256) s_rmin[i] = 0xFFFFFFFFu;
    if (tid == 0) s_cnt = 0;

    float acc[2][8][4];
    #pragma unroll
    for (int a = 0; a < 2; a++)
        #pragma unroll
        for (int b = 0; b < 8; b++)
            #pragma unroll
            for (int c = 0; c < 4; c++) acc[a][b][c] = 0.f;

    // stage loader: A+B each 128 rows x 64 cols bf16 = 1024 x 16B chunks, 4/thread
    #define LOAD_STAGE(s, kt) do {                                              \
        __nv_bfloat16* stA = sAb + (s) * BM * SSTR;                             \
        __nv_bfloat16* stB = sBb + (s) * BN * SSTR;                             \
        _Pragma("unroll")                                                       \
        for (int q = 0; q < 4; q++) {                                           \
            int ch = tid + q * 256;                                             \
            int r = ch >> 3, c8 = ch & 7;                                       \
            uint32_t da = smem_u32(&stA[r * SSTR + c8 * 8]);                    \
            const void* ga = &g_pooled_bf[(size_t)(rowBase + r) * DIM + (kt) + c8 * 8]; \
            asm volatile("cp.async.cg.shared.global [%0], [%1], 16;" :: "r"(da), "l"(ga)); \
            uint32_t db = smem_u32(&stB[r * SSTR + c8 * 8]);                    \
            const void* gb = &g_emb_bf[(size_t)(colBase + r) * DIM + (kt) + c8 * 8]; \
            asm volatile("cp.async.cg.shared.global [%0], [%1], 16;" :: "r"(db), "l"(gb)); \
        }                                                                       \
    } while (0)

    LOAD_STAGE(0, 0);
    asm volatile("cp.async.commit_group;" ::: "memory");

    const int NT = DIM / BK;   // 8
    for (int t = 0; t < NT; t++) {
        if (t + 1 < NT) LOAD_STAGE((t + 1) & 1, (t + 1) * BK);
        asm volatile("cp.async.commit_group;" ::: "memory");
        asm volatile("cp.async.wait_group 1;" ::: "memory");
        __syncthreads();
        int s = t & 1;
        __nv_bfloat16* stA = sAb + s * BM * SSTR;
        __nv_bfloat16* stB = sBb + s * BN * SSTR;
        #pragma unroll
        for (int ks = 0; ks < BK; ks += 16) {
            uint32_t af[2][4], bf[4][4];
            #pragma unroll
            for (int mf = 0; mf < 2; mf++) {
                uint32_t addr = smem_u32(
                    &stA[(wm * 32 + mf * 16 + (lane & 15)) * SSTR + ks + (lane >> 4) * 8]);
                asm volatile("ldmatrix.sync.aligned.m8n8.x4.shared.b16 {%0,%1,%2,%3},[%4];"
                             : "=r"(af[mf][0]), "=r"(af[mf][1]), "=r"(af[mf][2]), "=r"(af[mf][3])
                             : "r"(addr));
            }
            #pragma unroll
            for (int nb = 0; nb < 4; nb++) {
                uint32_t addr = smem_u32(
                    &stB[(wn * 64 + nb * 16 + (lane & 15)) * SSTR + ks + (lane >> 4) * 8]);
                asm volatile("ldmatrix.sync.aligned.m8n8.x4.shared.b16 {%0,%1,%2,%3},[%4];"
                             : "=r"(bf[nb][0]), "=r"(bf[nb][1]), "=r"(bf[nb][2]), "=r"(bf[nb][3])
                             : "r"(addr));
            }
            #pragma unroll
            for (int mf = 0; mf < 2; mf++) {
                #pragma unroll
                for (int nb = 0; nb < 4; nb++) {
                    asm volatile(
                        "mma.sync.aligned.m16n8k16.row.col.f32.bf16.bf16.f32 "
                        "{%0,%1,%2,%3}, {%4,%5,%6,%7}, {%8,%9}, {%0,%1,%2,%3};"
                        : "+f"(acc[mf][nb*2+0][0]), "+f"(acc[mf][nb*2+0][1]),
                          "+f"(acc[mf][nb*2+0][2]), "+f"(acc[mf][nb*2+0][3])
                        : "r"(af[mf][0]), "r"(af[mf][1]), "r"(af[mf][2]), "r"(af[mf][3]),
                          "r"(bf[nb][0]), "r"(bf[nb][2]));
                    asm volatile(
                        "mma.sync.aligned.m16n8k16.row.col.f32.bf16.bf16.f32 "
                        "{%0,%1,%2,%3}, {%4,%5,%6,%7}, {%8,%9}, {%0,%1,%2,%3};"
                        : "+f"(acc[mf][nb*2+1][0]), "+f"(acc[mf][nb*2+1][1]),
                          "+f"(acc[mf][nb*2+1][2]), "+f"(acc[mf][nb*2+1][3])
                        : "r"(af[mf][0]), "r"(af[mf][1]), "r"(af[mf][2]), "r"(af[mf][3]),
                          "r"(bf[nb][1]), "r"(bf[nb][3]));
                }
            }
        }
        __syncthreads();
    }

    // ---- epilogue: scores, per-row min, local candidate push ----
    unsigned mn[2][2] = {{0xFFFFFFFFu, 0xFFFFFFFFu}, {0xFFFFFFFFu, 0xFFFFFFFFu}};
    #pragma unroll
    for (int mf = 0; mf < 2; mf++) {
        #pragma unroll
        for (int nf = 0; nf < 8; nf++) {
            int c = colBase + wn * 64 + nf * 8 + (lane & 3) * 2;
            float e2a = g_e2[c], e2b = g_e2[c + 1];
            acc[mf][nf][0] = e2a - 2.f * acc[mf][nf][0];
            acc[mf][nf][1] = e2b - 2.f * acc[mf][nf][1];
            acc[mf][nf][2] = e2a - 2.f * acc[mf][nf][2];
            acc[mf][nf][3] = e2b - 2.f * acc[mf][nf][3];
            unsigned u;
            u = ord_u32(acc[mf][nf][0]); if (u < mn[mf][0]) mn[mf][0] = u;
            u = ord_u32(acc[mf][nf][1]); if (u < mn[mf][0]) mn[mf][0] = u;
            u = ord_u32(acc[mf][nf][2]); if (u < mn[mf][1]) mn[mf][1] = u;
            u = ord_u32(acc[mf][nf][3]); if (u < mn[mf][1]) mn[mf][1] = u;
        }
    }
    #pragma unroll
    for (int mf = 0; mf < 2; mf++)
        #pragma unroll
        for (int p = 0; p < 2; p++) {
            unsigned m = mn[mf][p];
            unsigned o = __shfl_xor_sync(0xffffffffu, m, 1); if (o < m) m = o;
            o = __shfl_xor_sync(0xffffffffu, m, 2); if (o < m) m = o;
            if ((lane & 3) == 0)
                atomicMin(&s_rmin[wm * 32 + mf * 16 + p * 8 + (lane >> 2)], m);
        }
    __syncthreads();

    if (tid < BM)
        g_tilemin[(size_t)(rowBase + tid) * NCTILE + blockIdx.x] = s_rmin[tid];

    uint2* cbuf = (uint2*)dyn;     // alias stage memory (done with it)
    #pragma unroll
    for (int mf = 0; mf < 2; mf++) {
        int lr_lo = wm * 32 + mf * 16 + (lane >> 2);
        float thr_lo = unord_f32(s_rmin[lr_lo]) + DELTA;
        float thr_hi = unord_f32(s_rmin[lr_lo + 8]) + DELTA;
        #pragma unroll
        for (int nf = 0; nf < 8; nf++) {
            int c = colBase + wn * 64 + nf * 8 + (lane & 3) * 2;
            #pragma unroll
            for (int q = 0; q < 4; q++) {
                float s = acc[mf][nf][q];
                int lr = (q < 2) ? lr_lo : lr_lo + 8;
                float thr = (q < 2) ? thr_lo : thr_hi;
                if (s <= thr) {
                    unsigned packed = ((unsigned)(rowBase + lr) << 13) | (unsigned)(c + (q & 1));
                    int slot = atomicAdd(&s_cnt, 1);
                    uint2 e = make_uint2(__float_as_uint(s), packed);
                    if (slot < CBUF_CAP) cbuf[slot] = e;
                    else {
                        int g = atomicAdd(&g_nc1, 1);
                        if (g < CAND1_CAP) g_cand1[g] = e;
                    }
                }
            }
        }
    }
    __syncthreads();
    if (tid == 0) {
        int n = s_cnt < CBUF_CAP ? s_cnt : CBUF_CAP;
        s_gbase = atomicAdd(&g_nc1, n);
        s_cnt = n;
    }
    __syncthreads();
    int n = s_cnt, gb = s_gbase;
    for (int i = tid; i < n; i += 256) {
        int g = gb + i;
        if (g < CAND1_CAP) g_cand1[g] = cbuf[i];
    }
}

// ---------------- global thresholds from tile minima (+ g_best init) ---------
__global__ void atvq_thr_kernel() {
    int warp = (blockIdx.x * blockDim.x + threadIdx.x) >> 5;
    int lane = threadIdx.x & 31;
    if (warp >= NROW) return;
    const unsigned* tm = &g_tilemin[(size_t)warp * NCTILE];
    unsigned m = tm[lane], o = tm[lane + 32];
    if (o < m) m = o;
    #pragma unroll
    for (int off = 16; off; off >>= 1) {
        o = __shfl_xor_sync(0xffffffffu, m, off); if (o < m) m = o;
    }
    if (lane == 0) {
        g_thr[warp] = unord_f32(m) + DELTA;
        g_best[warp] = ~0ULL;
    }
}

// ---------------- filter stage-1 candidates ----------------
__global__ void atvq_filter_kernel() {
    int n1 = g_nc1; if (n1 > CAND1_CAP) n1 = CAND1_CAP;
    int lane = threadIdx.x & 31;
    int gwarp = (blockIdx.x * blockDim.x + threadIdx.x) >> 5;
    int nwarp = (gridDim.x * blockDim.x) >> 5;
    for (int base = gwarp * 32; base < n1; base += nwarp * 32) {
        int i = base + lane;
        bool keep = false;
        uint2 e;
        if (i < n1) {
            e = g_cand1[i];
            keep = (__uint_as_float(e.x) <= g_thr[e.y >> 13]);
        }
        unsigned mask = __ballot_sync(0xffffffffu, keep);
        if (mask) {
            int cnt = __popc(mask);
            int pos = 0;
            if (lane == __ffs(mask) - 1) pos = atomicAdd(&g_ncand, cnt);
            pos = __shfl_sync(0xffffffffu, pos, __ffs(mask) - 1);
            if (keep) {
                int r = __popc(mask & ((1u << lane) - 1u));
                if (pos + r < CAND_CAP) g_cand[pos + r] = e.y;
            }
        }
    }
}

// ---------------- exact fp32 rerank ----------------
__global__ void atvq_rerank_kernel(const float* __restrict__ emb) {
    int gw = (blockIdx.x * blockDim.x + threadIdx.x) >> 5;
    int lane = threadIdx.x & 31;
    int nwarp = (gridDim.x * blockDim.x) >> 5;
    int n = g_ncand; if (n > CAND_CAP) n = CAND_CAP;
    for (int c = gw; c < n; c += nwarp) {
        unsigned e = g_cand[c];
        int row = e >> 13, k = e & (NCODE - 1);
        const float4* xp = (const float4*)&g_pooled[(size_t)row * DIM];
        const float4* ep = (const float4*)&emb[(size_t)k * DIM];
        float dot = 0.f;
        #pragma unroll
        for (int i = 0; i < 4; i++) {
            float4 a = xp[lane + i * 32];
            float4 b = ep[lane + i * 32];
            dot += a.x * b.x + a.y * b.y + a.z * b.z + a.w * b.w;
        }
        #pragma unroll
        for (int off = 16; off; off >>= 1) dot += __shfl_xor_sync(0xffffffffu, dot, off);
        if (lane == 0) {
            float s = g_e2[k] - 2.f * dot;
            unsigned long long key = ((unsigned long long)ord_u32(s) << 32) | (unsigned)k;
            atomicMin(&g_best[row], key);
        }
    }
}

// ---------------- gather + expand (float4 stores) + latent-loss partial ------
__global__ void atvq_gather_kernel(const float* __restrict__ emb,
                                   float* __restrict__ out) {
    int row = blockIdx.x;
    int t = threadIdx.x;
    int b = row >> 10, seg = row & 1023;
    unsigned long long bv = g_best[row];
    int k = (bv == ~0ULL) ? 0 : (int)(bv & (NCODE - 1));   // safety clamp

    // latent-loss partial (scalar path, 2 elems/thread)
    float e0 = emb[(size_t)k * DIM + t];
    float e1 = emb[(size_t)k * DIM + t + 256];
    float p0 = g_pooled[(size_t)row * DIM + t];
    float p1 = g_pooled[(size_t)row * DIM + t + 256];
    float d0 = e0 - p0, d1 = e1 - p1;
    float part = d0 * d0 + d1 * d1;

    // wide output expansion: 128 float4 per row, 8 rows
    size_t base4 = (((size_t)b * TLEN + (size_t)seg * SPAN) * DIM) >> 2;
    int c = t & 127;          // float4 index within the row
    int half = t >> 7;        // 0/1 -> rows {half, half+2, half+4, half+6}
    float4 v = ((const float4*)&emb[(size_t)k * DIM])[c];
    float4* o4 = (float4*)out;
    #pragma unroll
    for (int rr = 0; rr < 4; rr++)
        o4[base4 + (size_t)(half + rr * 2) * 128 + c] = v;

    #pragma unroll
    for (int off = 16; off; off >>= 1) part += __shfl_xor_sync(0xffffffffu, part, off);
    __shared__ float ws[8];
    int warp = t >> 5, lane = t & 31;
    if (lane == 0) ws[warp] = part;
    __syncthreads();
    if (t == 0) {
        float tot = 0.f;
        #pragma unroll
        for (int w = 0; w < 8; w++) tot += ws[w];
        g_partial[row] = tot;
    }
    if (t < SPAN)
        out[OUT_IDX_OFF + (size_t)b * TLEN + (size_t)seg * SPAN + t] = (float)k;
}

// ---------------- final scalar loss ----------------
__global__ void atvq_finalize_kernel(float* __restrict__ out) {
    __shared__ float sm[256];
    int t = threadIdx.x;
    float s = 0.f;
    for (int i = t; i < NROW; i += 256) s += g_partial[i];
    sm[t] = s;
    __syncthreads();
    for (int st = 128; st; st >>= 1) {
        if (t < st) sm[t] += sm[t + st];
        __syncthreads();
    }
    if (t == 0) {
        float elat = sm[0] / (float)((size_t)NROW * DIM);
        float bmean = (float)g_bcount / (float)(BATCH * TLEN);
        float bl = bmean - (1.0f / SPAN);
        bl = bl * bl;
        out[OUT_LOSS_OFF] = 0.25f * elat + 0.01f * bl;
    }
}

// ---------------- launcher ----------------
extern "C" void kernel_launch(void* const* d_in, const int* in_sizes, int n_in,
                              void* d_out, int out_size) {
    const float* x   = (const float*)d_in[0];
    const float* emb = (const float*)d_in[1];
    const float* Wb  = (const float*)d_in[2];
    const float* bb  = (const float*)d_in[3];
    float* out = (float*)d_out;

    static int attr_done = 0;
    if (!attr_done) {
        cudaFuncSetAttribute(atvq_hmma_kernel,
                             cudaFuncAttributeMaxDynamicSharedMemorySize, HMMA_DSMEM);
        attr_done = 1;
    }

    atvq_prep_kernel<<<NCODE / 8, 256>>>(emb);
    atvq_pool_boundary_kernel<<<NROW, 256>>>(x, Wb, bb, out);

    dim3 ggrid(NCODE / BN, NROW / BM);
    atvq_hmma_kernel<<<ggrid, 256, HMMA_DSMEM>>>();

    atvq_thr_kernel<<<NROW / 8, 256>>>();
    atvq_filter_kernel<<<1024, 256>>>();
    atvq_rerank_kernel<<<512, 256>>>(emb);
    atvq_gather_kernel<<<NROW, 256>>>(emb, out);
    atvq_finalize_kernel<<<1, 256>>>(out);
}

// round 16
// speedup vs baseline: 1.5377x; 1.0194x over previous
#include <cuda_runtime.h>
#include <cuda_bf16.h>
#include <cstdint>

// Problem constants
#define BATCH 16
#define TLEN 8192
#define DIM 512
#define SPAN 8
#define NSEG 1024
#define NROW 16384
#define NCODE 8192
#define NCTILE 64            // NCODE / BN

// Output layout (flattened tuple: quantized_out, total_loss, idx_out, boundaries)
#define OUT_Q_SIZE   ((size_t)BATCH*TLEN*DIM)
#define OUT_LOSS_OFF (OUT_Q_SIZE)
#define OUT_IDX_OFF  (OUT_LOSS_OFF + 1)
#define OUT_BND_OFF  (OUT_IDX_OFF + (size_t)BATCH*TLEN)

#define DELTA 0.125f
#define CAND1_CAP (1<<25)
#define CAND_CAP  (1<<21)
#define CBUF_CAP  2048

// GEMM tiling: BM=BN=128, BK=64, 8 warps (4x2), warp tile 32x64 (R6 proven config)
#define BM 128
#define BN 128
#define BK 64
#define SSTR 72                  // 64 + 8 pad, conflict-free ldmatrix
#define HMMA_DSMEM (2*(BM+BN)*SSTR*2)   // 73728 bytes

// ---------------- device scratch ----------------
__device__ float g_pooled[NROW * DIM];
__device__ __nv_bfloat16 g_pooled_bf[NROW * DIM];
__device__ __nv_bfloat16 g_emb_bf[NCODE * DIM];
__device__ float g_e2[NCODE];
__device__ unsigned g_tilemin[NROW * NCTILE];
__device__ float g_thr[NROW];
__device__ unsigned long long g_best[NROW];
__device__ float g_partial[NROW];
__device__ int g_bcount;
__device__ int g_nc1;
__device__ int g_ncand;
__device__ uint2 g_cand1[CAND1_CAP];
__device__ unsigned int g_cand[CAND_CAP];

// ---------------- helpers ----------------
__device__ __forceinline__ uint32_t smem_u32(const void* p) {
    uint32_t a;
    asm("{ .reg .u64 t; cvta.to.shared.u64 t, %1; cvt.u32.u64 %0, t; }" : "=r"(a) : "l"(p));
    return a;
}
__device__ __forceinline__ unsigned ord_u32(float s) {
    unsigned u = __float_as_uint(s);
    return (u & 0x80000000u) ? ~u : (u | 0x80000000u);
}
__device__ __forceinline__ float unord_f32(unsigned v) {
    unsigned u = (v & 0x80000000u) ? (v & 0x7FFFFFFFu) : ~v;
    return __uint_as_float(u);
}

// ---------------- fused: e2 + emb->bf16 + scalar init ----------------
__global__ void atvq_prep_kernel(const float* __restrict__ emb) {
    if (blockIdx.x == 0 && threadIdx.x == 0) { g_bcount = 0; g_nc1 = 0; g_ncand = 0; }
    int gw = (blockIdx.x * blockDim.x + threadIdx.x) >> 5;
    int lane = threadIdx.x & 31;
    if (gw >= NCODE) return;
    const float4* e = (const float4*)(emb + (size_t)gw * DIM);
    __nv_bfloat162* dst = (__nv_bfloat162*)(g_emb_bf + (size_t)gw * DIM);
    float s = 0.f;
    #pragma unroll
    for (int i = 0; i < 4; i++) {
        int c = lane + i * 32;
        float4 v = e[c];
        s += v.x * v.x + v.y * v.y + v.z * v.z + v.w * v.w;
        dst[c * 2 + 0] = __floats2bfloat162_rn(v.x, v.y);
        dst[c * 2 + 1] = __floats2bfloat162_rn(v.z, v.w);
    }
    #pragma unroll
    for (int off = 16; off; off >>= 1) s += __shfl_xor_sync(0xffffffffu, s, off);
    if (lane == 0) g_e2[gw] = s;
}

// ---------------- fused segment mean pool + boundary predictor ----------------
__global__ void atvq_pool_boundary_kernel(const float* __restrict__ x,
                                          const float* __restrict__ Wb,
                                          const float* __restrict__ bb,
                                          float* __restrict__ out) {
    int row = blockIdx.x;
    int b = row >> 10, seg = row & 1023;
    int t = threadIdx.x;
    float w0 = Wb[t], w1 = Wb[t + 256];
    const float* xb = x + ((size_t)b * TLEN + (size_t)seg * SPAN) * DIM;
    float s0 = 0.f, s1 = 0.f;
    float p[SPAN];
    #pragma unroll
    for (int r = 0; r < SPAN; r++) {
        float v0 = xb[(size_t)r * DIM + t];
        float v1 = xb[(size_t)r * DIM + t + 256];
        s0 += v0; s1 += v1;
        p[r] = v0 * w0 + v1 * w1;
    }
    float m0 = s0 * 0.125f, m1 = s1 * 0.125f;
    g_pooled[(size_t)row * DIM + t] = m0;
    g_pooled[(size_t)row * DIM + t + 256] = m1;
    g_pooled_bf[(size_t)row * DIM + t] = __float2bfloat16(m0);
    g_pooled_bf[(size_t)row * DIM + t + 256] = __float2bfloat16(m1);

    #pragma unroll
    for (int r = 0; r < SPAN; r++) {
        #pragma unroll
        for (int off = 16; off; off >>= 1) p[r] += __shfl_xor_sync(0xffffffffu, p[r], off);
    }
    __shared__ float ws[8][SPAN];
    int warp = t >> 5, lane = t & 31;
    if (lane == 0) {
        #pragma unroll
        for (int r = 0; r < SPAN; r++) ws[warp][r] = p[r];
    }
    __syncthreads();
    if (t < SPAN) {
        float sum = bb[0];
        #pragma unroll
        for (int w = 0; w < 8; w++) sum += ws[w][t];
        float bnd = (sum > 0.f) ? 1.f : 0.f;
        out[OUT_BND_OFF + (size_t)b * TLEN + (size_t)seg * SPAN + t] = bnd;
        if (bnd > 0.f) atomicAdd(&g_bcount, 1);
    }
}

// ---------------- bf16 HMMA approx-score GEMM + in-epilogue candidates -------
// BM=128 x BN=128, 8 warps (4x2), warp tile 32x64, BK=64, 2-stage cp.async
__global__ __launch_bounds__(256, 2)
void atvq_hmma_kernel() {
    extern __shared__ char dyn[];
    __nv_bfloat16* sAb = (__nv_bfloat16*)dyn;                       // 2 x BM*SSTR
    __nv_bfloat16* sBb = (__nv_bfloat16*)(dyn + 2 * BM * SSTR * 2); // 2 x BN*SSTR
    __shared__ unsigned s_rmin[BM];
    __shared__ int s_cnt, s_gbase;

    int tid = threadIdx.x, lane = tid & 31, wid = tid >> 5;
    int wm = wid & 3, wn = wid >> 2;            // 4 x 2 warp grid, 32x64 tiles
    int rowBase = blockIdx.y * BM;
    int colBase = blockIdx.x * BN;

    for (int i = tid; i < BM; i += 256) s_rmin[i] = 0xFFFFFFFFu;
    if (tid == 0) s_cnt = 0;

    float acc[2][8][4];
    #pragma unroll
    for (int a = 0; a < 2; a++)
        #pragma unroll
        for (int b = 0; b < 8; b++)
            #pragma unroll
            for (int c = 0; c < 4; c++) acc[a][b][c] = 0.f;

    // stage loader: A+B each 128 rows x 64 cols bf16 = 1024 x 16B chunks, 4/thread
    #define LOAD_STAGE(s, kt) do {                                              \
        __nv_bfloat16* stA = sAb + (s) * BM * SSTR;                             \
        __nv_bfloat16* stB = sBb + (s) * BN * SSTR;                             \
        _Pragma("unroll")                                                       \
        for (int q = 0; q < 4; q++) {                                           \
            int ch = tid + q * 256;                                             \
            int r = ch >> 3, c8 = ch & 7;                                       \
            uint32_t da = smem_u32(&stA[r * SSTR + c8 * 8]);                    \
            const void* ga = &g_pooled_bf[(size_t)(rowBase + r) * DIM + (kt) + c8 * 8]; \
            asm volatile("cp.async.ca.shared.global [%0], [%1], 16;" :: "r"(da), "l"(ga)); \
            uint32_t db = smem_u32(&stB[r * SSTR + c8 * 8]);                    \
            const void* gb = &g_emb_bf[(size_t)(colBase + r) * DIM + (kt) + c8 * 8]; \
            asm volatile("cp.async.ca.shared.global [%0], [%1], 16;" :: "r"(db), "l"(gb)); \
        }                                                                       \
    } while (0)

    LOAD_STAGE(0, 0);
    asm volatile("cp.async.commit_group;" ::: "memory");

    const int NT = DIM / BK;   // 8
    for (int t = 0; t < NT; t++) {
        if (t + 1 < NT) LOAD_STAGE((t + 1) & 1, (t + 1) * BK);
        asm volatile("cp.async.commit_group;" ::: "memory");
        asm volatile("cp.async.wait_group 1;" ::: "memory");
        __syncthreads();
        int s = t & 1;
        __nv_bfloat16* stA = sAb + s * BM * SSTR;
        __nv_bfloat16* stB = sBb + s * BN * SSTR;
        #pragma unroll
        for (int ks = 0; ks < BK; ks += 16) {
            uint32_t af[2][4], bf[4][4];
            #pragma unroll
            for (int mf = 0; mf < 2; mf++) {
                uint32_t addr = smem_u32(
                    &stA[(wm * 32 + mf * 16 + (lane & 15)) * SSTR + ks + (lane >> 4) * 8]);
                asm volatile("ldmatrix.sync.aligned.m8n8.x4.shared.b16 {%0,%1,%2,%3},[%4];"
                             : "=r"(af[mf][0]), "=r"(af[mf][1]), "=r"(af[mf][2]), "=r"(af[mf][3])
                             : "r"(addr));
            }
            #pragma unroll
            for (int nb = 0; nb < 4; nb++) {
                uint32_t addr = smem_u32(
                    &stB[(wn * 64 + nb * 16 + (lane & 15)) * SSTR + ks + (lane >> 4) * 8]);
                asm volatile("ldmatrix.sync.aligned.m8n8.x4.shared.b16 {%0,%1,%2,%3},[%4];"
                             : "=r"(bf[nb][0]), "=r"(bf[nb][1]), "=r"(bf[nb][2]), "=r"(bf[nb][3])
                             : "r"(addr));
            }
            #pragma unroll
            for (int mf = 0; mf < 2; mf++) {
                #pragma unroll
                for (int nb = 0; nb < 4; nb++) {
                    asm volatile(
                        "mma.sync.aligned.m16n8k16.row.col.f32.bf16.bf16.f32 "
                        "{%0,%1,%2,%3}, {%4,%5,%6,%7}, {%8,%9}, {%0,%1,%2,%3};"
                        : "+f"(acc[mf][nb*2+0][0]), "+f"(acc[mf][nb*2+0][1]),
                          "+f"(acc[mf][nb*2+0][2]), "+f"(acc[mf][nb*2+0][3])
                        : "r"(af[mf][0]), "r"(af[mf][1]), "r"(af[mf][2]), "r"(af[mf][3]),
                          "r"(bf[nb][0]), "r"(bf[nb][2]));
                    asm volatile(
                        "mma.sync.aligned.m16n8k16.row.col.f32.bf16.bf16.f32 "
                        "{%0,%1,%2,%3}, {%4,%5,%6,%7}, {%8,%9}, {%0,%1,%2,%3};"
                        : "+f"(acc[mf][nb*2+1][0]), "+f"(acc[mf][nb*2+1][1]),
                          "+f"(acc[mf][nb*2+1][2]), "+f"(acc[mf][nb*2+1][3])
                        : "r"(af[mf][0]), "r"(af[mf][1]), "r"(af[mf][2]), "r"(af[mf][3]),
                          "r"(bf[nb][1]), "r"(bf[nb][3]));
                }
            }
        }
        __syncthreads();
    }

    // ---- epilogue: scores, per-row min, local candidate push ----
    unsigned mn[2][2] = {{0xFFFFFFFFu, 0xFFFFFFFFu}, {0xFFFFFFFFu, 0xFFFFFFFFu}};
    #pragma unroll
    for (int mf = 0; mf < 2; mf++) {
        #pragma unroll
        for (int nf = 0; nf < 8; nf++) {
            int c = colBase + wn * 64 + nf * 8 + (lane & 3) * 2;
            float e2a = g_e2[c], e2b = g_e2[c + 1];
            acc[mf][nf][0] = e2a - 2.f * acc[mf][nf][0];
            acc[mf][nf][1] = e2b - 2.f * acc[mf][nf][1];
            acc[mf][nf][2] = e2a - 2.f * acc[mf][nf][2];
            acc[mf][nf][3] = e2b - 2.f * acc[mf][nf][3];
            unsigned u;
            u = ord_u32(acc[mf][nf][0]); if (u < mn[mf][0]) mn[mf][0] = u;
            u = ord_u32(acc[mf][nf][1]); if (u < mn[mf][0]) mn[mf][0] = u;
            u = ord_u32(acc[mf][nf][2]); if (u < mn[mf][1]) mn[mf][1] = u;
            u = ord_u32(acc[mf][nf][3]); if (u < mn[mf][1]) mn[mf][1] = u;
        }
    }
    #pragma unroll
    for (int mf = 0; mf < 2; mf++)
        #pragma unroll
        for (int p = 0; p < 2; p++) {
            unsigned m = mn[mf][p];
            unsigned o = __shfl_xor_sync(0xffffffffu, m, 1); if (o < m) m = o;
            o = __shfl_xor_sync(0xffffffffu, m, 2); if (o < m) m = o;
            if ((lane & 3) == 0)
                atomicMin(&s_rmin[wm * 32 + mf * 16 + p * 8 + (lane >> 2)], m);
        }
    __syncthreads();

    if (tid < BM)
        g_tilemin[(size_t)(rowBase + tid) * NCTILE + blockIdx.x] = s_rmin[tid];

    uint2* cbuf = (uint2*)dyn;     // alias stage memory (done with it)
    #pragma unroll
    for (int mf = 0; mf < 2; mf++) {
        int lr_lo = wm * 32 + mf * 16 + (lane >> 2);
        float thr_lo = unord_f32(s_rmin[lr_lo]) + DELTA;
        float thr_hi = unord_f32(s_rmin[lr_lo + 8]) + DELTA;
        #pragma unroll
        for (int nf = 0; nf < 8; nf++) {
            int c = colBase + wn * 64 + nf * 8 + (lane & 3) * 2;
            #pragma unroll
            for (int q = 0; q < 4; q++) {
                float s = acc[mf][nf][q];
                int lr = (q < 2) ? lr_lo : lr_lo + 8;
                float thr = (q < 2) ? thr_lo : thr_hi;
                if (s <= thr) {
                    unsigned packed = ((unsigned)(rowBase + lr) << 13) | (unsigned)(c + (q & 1));
                    int slot = atomicAdd(&s_cnt, 1);
                    uint2 e = make_uint2(__float_as_uint(s), packed);
                    if (slot < CBUF_CAP) cbuf[slot] = e;
                    else {
                        int g = atomicAdd(&g_nc1, 1);
                        if (g < CAND1_CAP) g_cand1[g] = e;
                    }
                }
            }
        }
    }
    __syncthreads();
    if (tid == 0) {
        int n = s_cnt < CBUF_CAP ? s_cnt : CBUF_CAP;
        s_gbase = atomicAdd(&g_nc1, n);
        s_cnt = n;
    }
    __syncthreads();
    int n = s_cnt, gb = s_gbase;
    for (int i = tid; i < n; i += 256) {
        int g = gb + i;
        if (g < CAND1_CAP) g_cand1[g] = cbuf[i];
    }
}

// ---------------- global thresholds from tile minima (+ g_best init) ---------
__global__ void atvq_thr_kernel() {
    int warp = (blockIdx.x * blockDim.x + threadIdx.x) >> 5;
    int lane = threadIdx.x & 31;
    if (warp >= NROW) return;
    const unsigned* tm = &g_tilemin[(size_t)warp * NCTILE];
    unsigned m = tm[lane], o = tm[lane + 32];
    if (o < m) m = o;
    #pragma unroll
    for (int off = 16; off; off >>= 1) {
        o = __shfl_xor_sync(0xffffffffu, m, off); if (o < m) m = o;
    }
    if (lane == 0) {
        g_thr[warp] = unord_f32(m) + DELTA;
        g_best[warp] = ~0ULL;
    }
}

// ---------------- filter stage-1 candidates ----------------
__global__ void atvq_filter_kernel() {
    int n1 = g_nc1; if (n1 > CAND1_CAP) n1 = CAND1_CAP;
    int lane = threadIdx.x & 31;
    int gwarp = (blockIdx.x * blockDim.x + threadIdx.x) >> 5;
    int nwarp = (gridDim.x * blockDim.x) >> 5;
    for (int base = gwarp * 32; base < n1; base += nwarp * 32) {
        int i = base + lane;
        bool keep = false;
        uint2 e;
        if (i < n1) {
            e = g_cand1[i];
            keep = (__uint_as_float(e.x) <= g_thr[e.y >> 13]);
        }
        unsigned mask = __ballot_sync(0xffffffffu, keep);
        if (mask) {
            int cnt = __popc(mask);
            int pos = 0;
            if (lane == __ffs(mask) - 1) pos = atomicAdd(&g_ncand, cnt);
            pos = __shfl_sync(0xffffffffu, pos, __ffs(mask) - 1);
            if (keep) {
                int r = __popc(mask & ((1u << lane) - 1u));
                if (pos + r < CAND_CAP) g_cand[pos + r] = e.y;
            }
        }
    }
}

// ---------------- exact fp32 rerank ----------------
__global__ void atvq_rerank_kernel(const float* __restrict__ emb) {
    int gw = (blockIdx.x * blockDim.x + threadIdx.x) >> 5;
    int lane = threadIdx.x & 31;
    int nwarp = (gridDim.x * blockDim.x) >> 5;
    int n = g_ncand; if (n > CAND_CAP) n = CAND_CAP;
    for (int c = gw; c < n; c += nwarp) {
        unsigned e = g_cand[c];
        int row = e >> 13, k = e & (NCODE - 1);
        const float4* xp = (const float4*)&g_pooled[(size_t)row * DIM];
        const float4* ep = (const float4*)&emb[(size_t)k * DIM];
        float dot = 0.f;
        #pragma unroll
        for (int i = 0; i < 4; i++) {
            float4 a = xp[lane + i * 32];
            float4 b = ep[lane + i * 32];
            dot += a.x * b.x + a.y * b.y + a.z * b.z + a.w * b.w;
        }
        #pragma unroll
        for (int off = 16; off; off >>= 1) dot += __shfl_xor_sync(0xffffffffu, dot, off);
        if (lane == 0) {
            float s = g_e2[k] - 2.f * dot;
            unsigned long long key = ((unsigned long long)ord_u32(s) << 32) | (unsigned)k;
            atomicMin(&g_best[row], key);
        }
    }
}

// ---------------- gather + expand (float4 stores) + latent-loss partial ------
__global__ void atvq_gather_kernel(const float* __restrict__ emb,
                                   float* __restrict__ out) {
    int row = blockIdx.x;
    int t = threadIdx.x;
    int b = row >> 10, seg = row & 1023;
    unsigned long long bv = g_best[row];
    int k = (bv == ~0ULL) ? 0 : (int)(bv & (NCODE - 1));   // safety clamp

    // latent-loss partial (scalar path, 2 elems/thread)
    float e0 = emb[(size_t)k * DIM + t];
    float e1 = emb[(size_t)k * DIM + t + 256];
    float p0 = g_pooled[(size_t)row * DIM + t];
    float p1 = g_pooled[(size_t)row * DIM + t + 256];
    float d0 = e0 - p0, d1 = e1 - p1;
    float part = d0 * d0 + d1 * d1;

    // wide output expansion: 128 float4 per row, 8 rows
    size_t base4 = (((size_t)b * TLEN + (size_t)seg * SPAN) * DIM) >> 2;
    int c = t & 127;          // float4 index within the row
    int half = t >> 7;        // 0/1 -> rows {half, half+2, half+4, half+6}
    float4 v = ((const float4*)&emb[(size_t)k * DIM])[c];
    float4* o4 = (float4*)out;
    #pragma unroll
    for (int rr = 0; rr < 4; rr++)
        o4[base4 + (size_t)(half + rr * 2) * 128 + c] = v;

    #pragma unroll
    for (int off = 16; off; off >>= 1) part += __shfl_xor_sync(0xffffffffu, part, off);
    __shared__ float ws[8];
    int warp = t >> 5, lane = t & 31;
    if (lane == 0) ws[warp] = part;
    __syncthreads();
    if (t == 0) {
        float tot = 0.f;
        #pragma unroll
        for (int w = 0; w < 8; w++) tot += ws[w];
        g_partial[row] = tot;
    }
    if (t < SPAN)
        out[OUT_IDX_OFF + (size_t)b * TLEN + (size_t)seg * SPAN + t] = (float)k;
}

// ---------------- final scalar loss ----------------
__global__ void atvq_finalize_kernel(float* __restrict__ out) {
    __shared__ float sm[256];
    int t = threadIdx.x;
    float s = 0.f;
    for (int i = t; i < NROW; i += 256) s += g_partial[i];
    sm[t] = s;
    __syncthreads();
    for (int st = 128; st; st >>= 1) {
        if (t < st) sm[t] += sm[t + st];
        __syncthreads();
    }
    if (t == 0) {
        float elat = sm[0] / (float)((size_t)NROW * DIM);
        float bmean = (float)g_bcount / (float)(BATCH * TLEN);
        float bl = bmean - (1.0f / SPAN);
        bl = bl * bl;
        out[OUT_LOSS_OFF] = 0.25f * elat + 0.01f * bl;
    }
}

// ---------------- launcher ----------------
extern "C" void kernel_launch(void* const* d_in, const int* in_sizes, int n_in,
                              void* d_out, int out_size) {
    const float* x   = (const float*)d_in[0];
    const float* emb = (const float*)d_in[1];
    const float* Wb  = (const float*)d_in[2];
    const float* bb  = (const float*)d_in[3];
    float* out = (float*)d_out;

    static int attr_done = 0;
    if (!attr_done) {
        cudaFuncSetAttribute(atvq_hmma_kernel,
                             cudaFuncAttributeMaxDynamicSharedMemorySize, HMMA_DSMEM);
        attr_done = 1;
    }

    atvq_prep_kernel<<<NCODE / 8, 256>>>(emb);
    atvq_pool_boundary_kernel<<<NROW, 256>>>(x, Wb, bb, out);

    dim3 ggrid(NCODE / BN, NROW / BM);
    atvq_hmma_kernel<<<ggrid, 256, HMMA_DSMEM>>>();

    atvq_thr_kernel<<<NROW / 8, 256>>>();
    atvq_filter_kernel<<<1024, 256>>>();
    atvq_rerank_kernel<<<512, 256>>>(emb);
    atvq_gather_kernel<<<NROW, 256>>>(emb, out);
    atvq_finalize_kernel<<<1, 256>>>(out);
}

// round 17
// speedup vs baseline: 1.5446x; 1.0045x over previous
#include <cuda_runtime.h>
#include <cuda_bf16.h>
#include <cstdint>

// Problem constants
#define BATCH 16
#define TLEN 8192
#define DIM 512
#define SPAN 8
#define NSEG 1024
#define NROW 16384
#define NCODE 8192
#define NCTILE 64            // NCODE / BN

// Output layout (flattened tuple: quantized_out, total_loss, idx_out, boundaries)
#define OUT_Q_SIZE   ((size_t)BATCH*TLEN*DIM)
#define OUT_LOSS_OFF (OUT_Q_SIZE)
#define OUT_IDX_OFF  (OUT_LOSS_OFF + 1)
#define OUT_BND_OFF  (OUT_IDX_OFF + (size_t)BATCH*TLEN)

#define DELTA 0.125f
#define CAND1_CAP (1<<25)
#define CAND_CAP  (1<<21)
#define CBUF_CAP  2048

// GEMM tiling: BM=BN=128, BK=64, 8 warps (4x2), warp tile 32x64, 3-stage pipeline
#define BM 128
#define BN 128
#define BK 64
#define NSTAGE 3
#define SSTR 72                  // 64 + 8 pad, conflict-free ldmatrix
#define STAGE_BYTES ((BM+BN)*SSTR*2)            // 36864
#define HMMA_DSMEM (NSTAGE*STAGE_BYTES)         // 110592 bytes

// ---------------- device scratch ----------------
__device__ float g_pooled[NROW * DIM];
__device__ __nv_bfloat16 g_pooled_bf[NROW * DIM];
__device__ __nv_bfloat16 g_emb_bf[NCODE * DIM];
__device__ float g_e2[NCODE];
__device__ unsigned g_tilemin[NROW * NCTILE];
__device__ float g_thr[NROW];
__device__ unsigned long long g_best[NROW];
__device__ float g_partial[NROW];
__device__ int g_bcount;
__device__ int g_nc1;
__device__ int g_ncand;
__device__ uint2 g_cand1[CAND1_CAP];
__device__ unsigned int g_cand[CAND_CAP];

// ---------------- helpers ----------------
__device__ __forceinline__ uint32_t smem_u32(const void* p) {
    uint32_t a;
    asm("{ .reg .u64 t; cvta.to.shared.u64 t, %1; cvt.u32.u64 %0, t; }" : "=r"(a) : "l"(p));
    return a;
}
__device__ __forceinline__ unsigned ord_u32(float s) {
    unsigned u = __float_as_uint(s);
    return (u & 0x80000000u) ? ~u : (u | 0x80000000u);
}
__device__ __forceinline__ float unord_f32(unsigned v) {
    unsigned u = (v & 0x80000000u) ? (v & 0x7FFFFFFFu) : ~v;
    return __uint_as_float(u);
}

// ---------------- fused: e2 + emb->bf16 + scalar init ----------------
__global__ void atvq_prep_kernel(const float* __restrict__ emb) {
    if (blockIdx.x == 0 && threadIdx.x == 0) { g_bcount = 0; g_nc1 = 0; g_ncand = 0; }
    int gw = (blockIdx.x * blockDim.x + threadIdx.x) >> 5;
    int lane = threadIdx.x & 31;
    if (gw >= NCODE) return;
    const float4* e = (const float4*)(emb + (size_t)gw * DIM);
    __nv_bfloat162* dst = (__nv_bfloat162*)(g_emb_bf + (size_t)gw * DIM);
    float s = 0.f;
    #pragma unroll
    for (int i = 0; i < 4; i++) {
        int c = lane + i * 32;
        float4 v = e[c];
        s += v.x * v.x + v.y * v.y + v.z * v.z + v.w * v.w;
        dst[c * 2 + 0] = __floats2bfloat162_rn(v.x, v.y);
        dst[c * 2 + 1] = __floats2bfloat162_rn(v.z, v.w);
    }
    #pragma unroll
    for (int off = 16; off; off >>= 1) s += __shfl_xor_sync(0xffffffffu, s, off);
    if (lane == 0) g_e2[gw] = s;
}

// ---------------- fused segment mean pool + boundary predictor ----------------
__global__ void atvq_pool_boundary_kernel(const float* __restrict__ x,
                                          const float* __restrict__ Wb,
                                          const float* __restrict__ bb,
                                          float* __restrict__ out) {
    int row = blockIdx.x;
    int b = row >> 10, seg = row & 1023;
    int t = threadIdx.x;
    float w0 = Wb[t], w1 = Wb[t + 256];
    const float* xb = x + ((size_t)b * TLEN + (size_t)seg * SPAN) * DIM;
    float s0 = 0.f, s1 = 0.f;
    float p[SPAN];
    #pragma unroll
    for (int r = 0; r < SPAN; r++) {
        float v0 = xb[(size_t)r * DIM + t];
        float v1 = xb[(size_t)r * DIM + t + 256];
        s0 += v0; s1 += v1;
        p[r] = v0 * w0 + v1 * w1;
    }
    float m0 = s0 * 0.125f, m1 = s1 * 0.125f;
    g_pooled[(size_t)row * DIM + t] = m0;
    g_pooled[(size_t)row * DIM + t + 256] = m1;
    g_pooled_bf[(size_t)row * DIM + t] = __float2bfloat16(m0);
    g_pooled_bf[(size_t)row * DIM + t + 256] = __float2bfloat16(m1);

    #pragma unroll
    for (int r = 0; r < SPAN; r++) {
        #pragma unroll
        for (int off = 16; off; off >>= 1) p[r] += __shfl_xor_sync(0xffffffffu, p[r], off);
    }
    __shared__ float ws[8][SPAN];
    int warp = t >> 5, lane = t & 31;
    if (lane == 0) {
        #pragma unroll
        for (int r = 0; r < SPAN; r++) ws[warp][r] = p[r];
    }
    __syncthreads();
    if (t < SPAN) {
        float sum = bb[0];
        #pragma unroll
        for (int w = 0; w < 8; w++) sum += ws[w][t];
        float bnd = (sum > 0.f) ? 1.f : 0.f;
        out[OUT_BND_OFF + (size_t)b * TLEN + (size_t)seg * SPAN + t] = bnd;
        if (bnd > 0.f) atomicAdd(&g_bcount, 1);
    }
}

// ---------------- bf16 HMMA approx-score GEMM + in-epilogue candidates -------
// BM=128 x BN=128, 8 warps (4x2), warp tile 32x64, BK=64, 3-stage cp.async,
// ONE __syncthreads per K-stage.
__global__ __launch_bounds__(256, 2)
void atvq_hmma_kernel() {
    extern __shared__ char dyn[];
    __shared__ unsigned s_rmin[BM];
    __shared__ int s_cnt, s_gbase;

    int tid = threadIdx.x, lane = tid & 31, wid = tid >> 5;
    int wm = wid & 3, wn = wid >> 2;            // 4 x 2 warp grid, 32x64 tiles
    int rowBase = blockIdx.y * BM;
    int colBase = blockIdx.x * BN;

    for (int i = tid; i < BM; i += 256) s_rmin[i] = 0xFFFFFFFFu;
    if (tid == 0) s_cnt = 0;

    float acc[2][8][4];
    #pragma unroll
    for (int a = 0; a < 2; a++)
        #pragma unroll
        for (int b = 0; b < 8; b++)
            #pragma unroll
            for (int c = 0; c < 4; c++) acc[a][b][c] = 0.f;

    // stage s: A at dyn + s*STAGE_BYTES, B at A + BM*SSTR*2
    #define LOAD_STAGE(s, kt) do {                                              \
        char* stA = dyn + (s) * STAGE_BYTES;                                    \
        char* stB = stA + BM * SSTR * 2;                                        \
        _Pragma("unroll")                                                       \
        for (int q = 0; q < 4; q++) {                                           \
            int ch = tid + q * 256;                                             \
            int r = ch >> 3, c8 = ch & 7;                                       \
            uint32_t da = smem_u32(stA + (r * SSTR + c8 * 8) * 2);              \
            const void* ga = &g_pooled_bf[(size_t)(rowBase + r) * DIM + (kt) + c8 * 8]; \
            asm volatile("cp.async.ca.shared.global [%0], [%1], 16;" :: "r"(da), "l"(ga)); \
            uint32_t db = smem_u32(stB + (r * SSTR + c8 * 8) * 2);              \
            const void* gb = &g_emb_bf[(size_t)(colBase + r) * DIM + (kt) + c8 * 8]; \
            asm volatile("cp.async.ca.shared.global [%0], [%1], 16;" :: "r"(db), "l"(gb)); \
        }                                                                       \
    } while (0)

    LOAD_STAGE(0, 0);
    asm volatile("cp.async.commit_group;" ::: "memory");
    LOAD_STAGE(1, BK);
    asm volatile("cp.async.commit_group;" ::: "memory");

    const int NT = DIM / BK;   // 8
    #pragma unroll 1
    for (int t = 0; t < NT; t++) {
        asm volatile("cp.async.wait_group 1;" ::: "memory");   // stage t arrived
        __syncthreads();   // data visible; all warps done with stage t-1 (its buffer = (t+2)%3)
        if (t + 2 < NT) {
            LOAD_STAGE((t + 2) % NSTAGE, (t + 2) * BK);
        }
        asm volatile("cp.async.commit_group;" ::: "memory");
        int s = t % NSTAGE;
        __nv_bfloat16* stA = (__nv_bfloat16*)(dyn + s * STAGE_BYTES);
        __nv_bfloat16* stB = stA + BM * SSTR;
        #pragma unroll
        for (int ks = 0; ks < BK; ks += 16) {
            uint32_t af[2][4], bf[4][4];
            #pragma unroll
            for (int mf = 0; mf < 2; mf++) {
                uint32_t addr = smem_u32(
                    &stA[(wm * 32 + mf * 16 + (lane & 15)) * SSTR + ks + (lane >> 4) * 8]);
                asm volatile("ldmatrix.sync.aligned.m8n8.x4.shared.b16 {%0,%1,%2,%3},[%4];"
                             : "=r"(af[mf][0]), "=r"(af[mf][1]), "=r"(af[mf][2]), "=r"(af[mf][3])
                             : "r"(addr));
            }
            #pragma unroll
            for (int nb = 0; nb < 4; nb++) {
                uint32_t addr = smem_u32(
                    &stB[(wn * 64 + nb * 16 + (lane & 15)) * SSTR + ks + (lane >> 4) * 8]);
                asm volatile("ldmatrix.sync.aligned.m8n8.x4.shared.b16 {%0,%1,%2,%3},[%4];"
                             : "=r"(bf[nb][0]), "=r"(bf[nb][1]), "=r"(bf[nb][2]), "=r"(bf[nb][3])
                             : "r"(addr));
            }
            #pragma unroll
            for (int mf = 0; mf < 2; mf++) {
                #pragma unroll
                for (int nb = 0; nb < 4; nb++) {
                    asm volatile(
                        "mma.sync.aligned.m16n8k16.row.col.f32.bf16.bf16.f32 "
                        "{%0,%1,%2,%3}, {%4,%5,%6,%7}, {%8,%9}, {%0,%1,%2,%3};"
                        : "+f"(acc[mf][nb*2+0][0]), "+f"(acc[mf][nb*2+0][1]),
                          "+f"(acc[mf][nb*2+0][2]), "+f"(acc[mf][nb*2+0][3])
                        : "r"(af[mf][0]), "r"(af[mf][1]), "r"(af[mf][2]), "r"(af[mf][3]),
                          "r"(bf[nb][0]), "r"(bf[nb][2]));
                    asm volatile(
                        "mma.sync.aligned.m16n8k16.row.col.f32.bf16.bf16.f32 "
                        "{%0,%1,%2,%3}, {%4,%5,%6,%7}, {%8,%9}, {%0,%1,%2,%3};"
                        : "+f"(acc[mf][nb*2+1][0]), "+f"(acc[mf][nb*2+1][1]),
                          "+f"(acc[mf][nb*2+1][2]), "+f"(acc[mf][nb*2+1][3])
                        : "r"(af[mf][0]), "r"(af[mf][1]), "r"(af[mf][2]), "r"(af[mf][3]),
                          "r"(bf[nb][1]), "r"(bf[nb][3]));
                }
            }
        }
    }
    __syncthreads();   // all compute done before epilogue reuses dyn as cbuf

    // ---- epilogue: scores, per-row min, local candidate push ----
    unsigned mn[2][2] = {{0xFFFFFFFFu, 0xFFFFFFFFu}, {0xFFFFFFFFu, 0xFFFFFFFFu}};
    #pragma unroll
    for (int mf = 0; mf < 2; mf++) {
        #pragma unroll
        for (int nf = 0; nf < 8; nf++) {
            int c = colBase + wn * 64 + nf * 8 + (lane & 3) * 2;
            float e2a = g_e2[c], e2b = g_e2[c + 1];
            acc[mf][nf][0] = e2a - 2.f * acc[mf][nf][0];
            acc[mf][nf][1] = e2b - 2.f * acc[mf][nf][1];
            acc[mf][nf][2] = e2a - 2.f * acc[mf][nf][2];
            acc[mf][nf][3] = e2b - 2.f * acc[mf][nf][3];
            unsigned u;
            u = ord_u32(acc[mf][nf][0]); if (u < mn[mf][0]) mn[mf][0] = u;
            u = ord_u32(acc[mf][nf][1]); if (u < mn[mf][0]) mn[mf][0] = u;
            u = ord_u32(acc[mf][nf][2]); if (u < mn[mf][1]) mn[mf][1] = u;
            u = ord_u32(acc[mf][nf][3]); if (u < mn[mf][1]) mn[mf][1] = u;
        }
    }
    #pragma unroll
    for (int mf = 0; mf < 2; mf++)
        #pragma unroll
        for (int p = 0; p < 2; p++) {
            unsigned m = mn[mf][p];
            unsigned o = __shfl_xor_sync(0xffffffffu, m, 1); if (o < m) m = o;
            o = __shfl_xor_sync(0xffffffffu, m, 2); if (o < m) m = o;
            if ((lane & 3) == 0)
                atomicMin(&s_rmin[wm * 32 + mf * 16 + p * 8 + (lane >> 2)], m);
        }
    __syncthreads();

    if (tid < BM)
        g_tilemin[(size_t)(rowBase + tid) * NCTILE + blockIdx.x] = s_rmin[tid];

    uint2* cbuf = (uint2*)dyn;     // alias stage memory (done with it)
    #pragma unroll
    for (int mf = 0; mf < 2; mf++) {
        int lr_lo = wm * 32 + mf * 16 + (lane >> 2);
        float thr_lo = unord_f32(s_rmin[lr_lo]) + DELTA;
        float thr_hi = unord_f32(s_rmin[lr_lo + 8]) + DELTA;
        #pragma unroll
        for (int nf = 0; nf < 8; nf++) {
            int c = colBase + wn * 64 + nf * 8 + (lane & 3) * 2;
            #pragma unroll
            for (int q = 0; q < 4; q++) {
                float s = acc[mf][nf][q];
                int lr = (q < 2) ? lr_lo : lr_lo + 8;
                float thr = (q < 2) ? thr_lo : thr_hi;
                if (s <= thr) {
                    unsigned packed = ((unsigned)(rowBase + lr) << 13) | (unsigned)(c + (q & 1));
                    int slot = atomicAdd(&s_cnt, 1);
                    uint2 e = make_uint2(__float_as_uint(s), packed);
                    if (slot < CBUF_CAP) cbuf[slot] = e;
                    else {
                        int g = atomicAdd(&g_nc1, 1);
                        if (g < CAND1_CAP) g_cand1[g] = e;
                    }
                }
            }
        }
    }
    __syncthreads();
    if (tid == 0) {
        int n = s_cnt < CBUF_CAP ? s_cnt : CBUF_CAP;
        s_gbase = atomicAdd(&g_nc1, n);
        s_cnt = n;
    }
    __syncthreads();
    int n = s_cnt, gb = s_gbase;
    for (int i = tid; i < n; i += 256) {
        int g = gb + i;
        if (g < CAND1_CAP) g_cand1[g] = cbuf[i];
    }
}

// ---------------- global thresholds from tile minima (+ g_best init) ---------
__global__ void atvq_thr_kernel() {
    int warp = (blockIdx.x * blockDim.x + threadIdx.x) >> 5;
    int lane = threadIdx.x & 31;
    if (warp >= NROW) return;
    const unsigned* tm = &g_tilemin[(size_t)warp * NCTILE];
    unsigned m = tm[lane], o = tm[lane + 32];
    if (o < m) m = o;
    #pragma unroll
    for (int off = 16; off; off >>= 1) {
        o = __shfl_xor_sync(0xffffffffu, m, off); if (o < m) m = o;
    }
    if (lane == 0) {
        g_thr[warp] = unord_f32(m) + DELTA;
        g_best[warp] = ~0ULL;
    }
}

// ---------------- filter stage-1 candidates ----------------
__global__ void atvq_filter_kernel() {
    int n1 = g_nc1; if (n1 > CAND1_CAP) n1 = CAND1_CAP;
    int lane = threadIdx.x & 31;
    int gwarp = (blockIdx.x * blockDim.x + threadIdx.x) >> 5;
    int nwarp = (gridDim.x * blockDim.x) >> 5;
    for (int base = gwarp * 32; base < n1; base += nwarp * 32) {
        int i = base + lane;
        bool keep = false;
        uint2 e;
        if (i < n1) {
            e = g_cand1[i];
            keep = (__uint_as_float(e.x) <= g_thr[e.y >> 13]);
        }
        unsigned mask = __ballot_sync(0xffffffffu, keep);
        if (mask) {
            int cnt = __popc(mask);
            int pos = 0;
            if (lane == __ffs(mask) - 1) pos = atomicAdd(&g_ncand, cnt);
            pos = __shfl_sync(0xffffffffu, pos, __ffs(mask) - 1);
            if (keep) {
                int r = __popc(mask & ((1u << lane) - 1u));
                if (pos + r < CAND_CAP) g_cand[pos + r] = e.y;
            }
        }
    }
}

// ---------------- exact fp32 rerank ----------------
__global__ void atvq_rerank_kernel(const float* __restrict__ emb) {
    int gw = (blockIdx.x * blockDim.x + threadIdx.x) >> 5;
    int lane = threadIdx.x & 31;
    int nwarp = (gridDim.x * blockDim.x) >> 5;
    int n = g_ncand; if (n > CAND_CAP) n = CAND_CAP;
    for (int c = gw; c < n; c += nwarp) {
        unsigned e = g_cand[c];
        int row = e >> 13, k = e & (NCODE - 1);
        const float4* xp = (const float4*)&g_pooled[(size_t)row * DIM];
        const float4* ep = (const float4*)&emb[(size_t)k * DIM];
        float dot = 0.f;
        #pragma unroll
        for (int i = 0; i < 4; i++) {
            float4 a = xp[lane + i * 32];
            float4 b = ep[lane + i * 32];
            dot += a.x * b.x + a.y * b.y + a.z * b.z + a.w * b.w;
        }
        #pragma unroll
        for (int off = 16; off; off >>= 1) dot += __shfl_xor_sync(0xffffffffu, dot, off);
        if (lane == 0) {
            float s = g_e2[k] - 2.f * dot;
            unsigned long long key = ((unsigned long long)ord_u32(s) << 32) | (unsigned)k;
            atomicMin(&g_best[row], key);
        }
    }
}

// ---------------- gather + expand (float4 stores) + latent-loss partial ------
__global__ void atvq_gather_kernel(const float* __restrict__ emb,
                                   float* __restrict__ out) {
    int row = blockIdx.x;
    int t = threadIdx.x;
    int b = row >> 10, seg = row & 1023;
    unsigned long long bv = g_best[row];
    int k = (bv == ~0ULL) ? 0 : (int)(bv & (NCODE - 1));   // safety clamp

    float e0 = emb[(size_t)k * DIM + t];
    float e1 = emb[(size_t)k * DIM + t + 256];
    float p0 = g_pooled[(size_t)row * DIM + t];
    float p1 = g_pooled[(size_t)row * DIM + t + 256];
    float d0 = e0 - p0, d1 = e1 - p1;
    float part = d0 * d0 + d1 * d1;

    size_t base4 = (((size_t)b * TLEN + (size_t)seg * SPAN) * DIM) >> 2;
    int c = t & 127;
    int half = t >> 7;
    float4 v = ((const float4*)&emb[(size_t)k * DIM])[c];
    float4* o4 = (float4*)out;
    #pragma unroll
    for (int rr = 0; rr < 4; rr++)
        o4[base4 + (size_t)(half + rr * 2) * 128 + c] = v;

    #pragma unroll
    for (int off = 16; off; off >>= 1) part += __shfl_xor_sync(0xffffffffu, part, off);
    __shared__ float ws[8];
    int warp = t >> 5, lane = t & 31;
    if (lane == 0) ws[warp] = part;
    __syncthreads();
    if (t == 0) {
        float tot = 0.f;
        #pragma unroll
        for (int w = 0; w < 8; w++) tot += ws[w];
        g_partial[row] = tot;
    }
    if (t < SPAN)
        out[OUT_IDX_OFF + (size_t)b * TLEN + (size_t)seg * SPAN + t] = (float)k;
}

// ---------------- final scalar loss ----------------
__global__ void atvq_finalize_kernel(float* __restrict__ out) {
    __shared__ float sm[256];
    int t = threadIdx.x;
    float s = 0.f;
    for (int i = t; i < NROW; i += 256) s += g_partial[i];
    sm[t] = s;
    __syncthreads();
    for (int st = 128; st; st >>= 1) {
        if (t < st) sm[t] += sm[t + st];
        __syncthreads();
    }
    if (t == 0) {
        float elat = sm[0] / (float)((size_t)NROW * DIM);
        float bmean = (float)g_bcount / (float)(BATCH * TLEN);
        float bl = bmean - (1.0f / SPAN);
        bl = bl * bl;
        out[OUT_LOSS_OFF] = 0.25f * elat + 0.01f * bl;
    }
}

// ---------------- launcher ----------------
extern "C" void kernel_launch(void* const* d_in, const int* in_sizes, int n_in,
                              void* d_out, int out_size) {
    const float* x   = (const float*)d_in[0];
    const float* emb = (const float*)d_in[1];
    const float* Wb  = (const float*)d_in[2];
    const float* bb  = (const float*)d_in[3];
    float* out = (float*)d_out;

    static int attr_done = 0;
    if (!attr_done) {
        cudaFuncSetAttribute(atvq_hmma_kernel,
                             cudaFuncAttributeMaxDynamicSharedMemorySize, HMMA_DSMEM);
        attr_done = 1;
    }

    atvq_prep_kernel<<<NCODE / 8, 256>>>(emb);
    atvq_pool_boundary_kernel<<<NROW, 256>>>(x, Wb, bb, out);

    dim3 ggrid(NCODE / BN, NROW / BM);
    atvq_hmma_kernel<<<ggrid, 256, HMMA_DSMEM>>>();

    atvq_thr_kernel<<<NROW / 8, 256>>>();
    atvq_filter_kernel<<<1024, 256>>>();
    atvq_rerank_kernel<<<512, 256>>>(emb);
    atvq_gather_kernel<<<NROW, 256>>>(emb, out);
    atvq_finalize_kernel<<<1, 256>>>(out);
}